// round 6
// baseline (speedup 1.0000x reference)
#include <cuda_runtime.h>
#include <cuda_bf16.h>
#include <float.h>

// Problem constants
#define B_  8
#define T_  512
#define D_  256
#define S_  64
#define P_  1024
#define R_  12

// Scratch (device globals — no allocation allowed)
__device__ float g_sp[B_ * S_ * D_];        // span-pooled features [B,S,D]
__device__ float g_U [B_ * S_ * R_ * D_];   // U[b,s,r,e] = sum_d sp[b,s,d]*Wb[r,d,e]
__device__ float g_Lh[B_ * S_ * R_];        // head linear term
__device__ float g_Lt[B_ * S_ * R_];        // tail linear term

// ---------------------------------------------------------------------------
// f32x2 packed-math helpers (sm_10x: fma.rn.f32x2 — 2x fp32 FMA throughput;
// ptxas never auto-fuses this from C++, must come via PTX)
// ---------------------------------------------------------------------------
__device__ __forceinline__ unsigned long long ffma2_(unsigned long long a,
                                                     unsigned long long b,
                                                     unsigned long long c) {
    unsigned long long d;
    asm("fma.rn.f32x2 %0, %1, %2, %3;" : "=l"(d) : "l"(a), "l"(b), "l"(c));
    return d;
}
__device__ __forceinline__ unsigned long long pack_dup(float x) {
    unsigned long long d;
    unsigned int xi = __float_as_uint(x);
    asm("mov.b64 %0, {%1, %1};" : "=l"(d) : "r"(xi));
    return d;
}
__device__ __forceinline__ float2 unpack2(unsigned long long v) {
    float2 f;
    asm("mov.b64 {%0, %1}, %2;" : "=f"(f.x), "=f"(f.y) : "l"(v));
    return f;
}

// ---------------------------------------------------------------------------
// Kernel 1: ragged span max-pool + per-span linear projections
// grid = B*S blocks, 256 threads (one thread per feature dim).
// Span length is bounded (len < 12 => <= 13 rows), so the max loop is fully
// unrolled with predicated loads: 13 independent LDGs in flight (MLP=13)
// instead of a serial MLP=1 dynamic loop.
// ---------------------------------------------------------------------------
#define MAX_SPAN 13

__global__ void pool_linear_kernel(const float* __restrict__ encoded,
                                   const float* __restrict__ W_linear,
                                   const int*   __restrict__ span_starts,
                                   const int*   __restrict__ span_lens)
{
    int bs = blockIdx.x;             // 0..511
    int b  = bs >> 6;
    int s  = bs & (S_ - 1);
    int d  = threadIdx.x;

    int start = span_starts[b * S_ + s];
    int len   = span_lens  [b * S_ + s];
    int end   = start + len + 1;     // reference guarantees end <= T
    if (end > T_) end = T_;
    int n = end - start;             // 1..13

    const float* ep = encoded + ((size_t)b * T_ + start) * D_ + d;
    float m = -FLT_MAX;
    #pragma unroll
    for (int i = 0; i < MAX_SPAN; ++i) {
        float v = (i < n) ? ep[(size_t)i * D_] : -FLT_MAX;
        m = fmaxf(m, v);
    }

    __shared__ float sm[D_];
    sm[d] = m;
    g_sp[(size_t)bs * D_ + d] = m;
    __syncthreads();

    // 24 dot products (12 head-part + 12 tail-part), 8 warps -> 3 each
    int w    = threadIdx.x >> 5;
    int lane = threadIdx.x & 31;
    for (int j = w; j < 24; j += 8) {
        int r    = j % R_;
        int part = j / R_;        // 0 = head half of W_linear, 1 = tail half
        float acc = 0.f;
        #pragma unroll
        for (int i = 0; i < 8; ++i) {
            int dd = i * 32 + lane;
            acc = fmaf(sm[dd], W_linear[(size_t)(part * D_ + dd) * R_ + r], acc);
        }
        #pragma unroll
        for (int o = 16; o; o >>= 1)
            acc += __shfl_xor_sync(0xFFFFFFFFu, acc, o);
        if (lane == 0) {
            if (part) g_Lt[bs * R_ + r] = acc;
            else      g_Lh[bs * R_ + r] = acc;
        }
    }
}

// ---------------------------------------------------------------------------
// Kernel 2: U[b,s,r,e] = sum_d sp[b,s,d] * Wb[r,d,e]
// 12 GEMMs: A = g_sp [512 x 256], B = Wb[r] [256 x 256] -> C_r [512 x 256]
// 64x64 block tile, BK=32, 256 threads, 4x4 register tile, f32x2 FMA.
// 384 blocks / occ 2 -> ~2.6 blocks per SM (vs 96 blocks leaving 52 SMs idle).
// ---------------------------------------------------------------------------
#define BM 64
#define BN 64
#define BK 32

__global__ __launch_bounds__(256, 2)
void ugemm_kernel(const float* __restrict__ Wb)
{
    const int r  = blockIdx.z;
    const int m0 = blockIdx.y * BM;
    const int n0 = blockIdx.x * BN;

    const float* A  = g_sp;                         // [512, 256] row-major
    const float* Bm = Wb + (size_t)r * D_ * D_;     // [256, 256] row-major

    __shared__ float As[BK][BM + 4];   // transposed: As[k][m], row = 272B (16B-aligned)
    __shared__ float Bs[BK][BN + 4];

    const int tid = threadIdx.x;       // 0..255

    // global-load mapping (2x float4 per operand per thread per slab)
    const int a_row = tid >> 2;            // 0..63
    const int a_k   = (tid & 3) * 8;       // 0,8,16,24
    const int b_k   = tid >> 3;            // 0..31
    const int b_col = (tid & 7) * 8;       // 0..56

    // compute mapping: 4x4 register tile
    const int tm  = (tid >> 4) * 4;        // 0..60
    const int tn4 = (tid & 15) * 4;        // 0..60

    unsigned long long acc[4][2];
    #pragma unroll
    for (int i = 0; i < 4; ++i) { acc[i][0] = 0ULL; acc[i][1] = 0ULL; }

    // prefetch slab 0
    float4 pa0 = *(const float4*)&A [(size_t)(m0 + a_row) * D_ + a_k];
    float4 pa1 = *(const float4*)&A [(size_t)(m0 + a_row) * D_ + a_k + 4];
    float4 pb0 = *(const float4*)&Bm[(size_t)b_k * D_ + n0 + b_col];
    float4 pb1 = *(const float4*)&Bm[(size_t)b_k * D_ + n0 + b_col + 4];

    for (int k0 = 0; k0 < D_; k0 += BK) {
        // commit staged slab to smem (A transposed)
        As[a_k + 0][a_row] = pa0.x;
        As[a_k + 1][a_row] = pa0.y;
        As[a_k + 2][a_row] = pa0.z;
        As[a_k + 3][a_row] = pa0.w;
        As[a_k + 4][a_row] = pa1.x;
        As[a_k + 5][a_row] = pa1.y;
        As[a_k + 6][a_row] = pa1.z;
        As[a_k + 7][a_row] = pa1.w;
        *(float4*)&Bs[b_k][b_col]     = pb0;
        *(float4*)&Bs[b_k][b_col + 4] = pb1;
        __syncthreads();

        // prefetch next slab (LDG latency overlaps the ~1K-cycle compute phase)
        if (k0 + BK < D_) {
            pa0 = *(const float4*)&A [(size_t)(m0 + a_row) * D_ + k0 + BK + a_k];
            pa1 = *(const float4*)&A [(size_t)(m0 + a_row) * D_ + k0 + BK + a_k + 4];
            pb0 = *(const float4*)&Bm[(size_t)(k0 + BK + b_k) * D_ + n0 + b_col];
            pb1 = *(const float4*)&Bm[(size_t)(k0 + BK + b_k) * D_ + n0 + b_col + 4];
        }

        #pragma unroll
        for (int k = 0; k < BK; ++k) {
            float4 av = *(const float4*)&As[k][tm];              // 2-addr broadcast / warp
            ulonglong2 bq = *(const ulonglong2*)&Bs[k][tn4];     // 16 lanes x 16B, conflict-free
            unsigned long long bb0 = bq.x, bb1 = bq.y;
            float aa[4] = {av.x, av.y, av.z, av.w};
            #pragma unroll
            for (int i = 0; i < 4; ++i) {
                unsigned long long ad = pack_dup(aa[i]);
                acc[i][0] = ffma2_(ad, bb0, acc[i][0]);
                acc[i][1] = ffma2_(ad, bb1, acc[i][1]);
            }
        }
        __syncthreads();
    }

    // store: g_U[((m0+tm+i)*R + r)*D + n0 + tn4 .. +3]
    #pragma unroll
    for (int i = 0; i < 4; ++i) {
        float2 c01 = unpack2(acc[i][0]);
        float2 c23 = unpack2(acc[i][1]);
        size_t base = ((size_t)(m0 + tm + i) * R_ + r) * D_;
        *(float4*)&g_U[base + n0 + tn4] = make_float4(c01.x, c01.y, c23.x, c23.y);
    }
}

// ---------------------------------------------------------------------------
// Kernel 3: per-pair score. One warp per pair.
// score[r] = Lh[head,r] + Lt[tail,r] + bias[r] + dot(U[head,r,:], sp[tail,:])
// out = sigmoid(score)
// ---------------------------------------------------------------------------
__global__ void pair_kernel(const int*   __restrict__ pair_head,
                            const int*   __restrict__ pair_tail,
                            const float* __restrict__ b_linear,
                            float*       __restrict__ out)
{
    int g    = blockIdx.x * 8 + (threadIdx.x >> 5);   // global pair id 0..8191
    int lane = threadIdx.x & 31;
    int b    = g >> 10;
    int p    = g & (P_ - 1);

    int h = pair_head[b * P_ + p];
    int t = pair_tail[b * P_ + p];

    const float* tvp = g_sp + (size_t)(b * S_ + t) * D_;
    float tv[8];
    #pragma unroll
    for (int i = 0; i < 8; ++i) tv[i] = tvp[i * 32 + lane];

    const float* Up  = g_U  + (size_t)(b * S_ + h) * R_ * D_;
    const float* Lhp = g_Lh + (b * S_ + h) * R_;
    const float* Ltp = g_Lt + (b * S_ + t) * R_;

    #pragma unroll
    for (int r = 0; r < R_; ++r) {
        float acc = 0.f;
        const float* ur = Up + r * D_;
        #pragma unroll
        for (int i = 0; i < 8; ++i)
            acc = fmaf(ur[i * 32 + lane], tv[i], acc);
        #pragma unroll
        for (int o = 16; o; o >>= 1)
            acc += __shfl_xor_sync(0xFFFFFFFFu, acc, o);
        if (lane == 0) {
            float x = acc + Lhp[r] + Ltp[r] + b_linear[r];
            out[(size_t)(b * P_ + p) * R_ + r] = 1.f / (1.f + __expf(-x));
        }
    }
}

// ---------------------------------------------------------------------------
extern "C" void kernel_launch(void* const* d_in, const int* in_sizes, int n_in,
                              void* d_out, int out_size)
{
    const float* encoded     = (const float*)d_in[0];  // [8,512,256]
    const float* W_linear    = (const float*)d_in[1];  // [512,12]
    const float* b_linear    = (const float*)d_in[2];  // [12]
    const float* W_bilinear  = (const float*)d_in[3];  // [12,256,256]
    const int*   span_starts = (const int*)  d_in[4];  // [8,64]
    const int*   span_lens   = (const int*)  d_in[5];  // [8,64]
    const int*   pair_head   = (const int*)  d_in[6];  // [8,1024]
    const int*   pair_tail   = (const int*)  d_in[7];  // [8,1024]
    float*       out         = (float*)d_out;          // [8,1024,12]

    pool_linear_kernel<<<B_ * S_, 256>>>(encoded, W_linear, span_starts, span_lens);

    dim3 ggrid(D_ / BN, (B_ * S_) / BM, R_);  // (4, 8, 12) = 384 blocks
    ugemm_kernel<<<ggrid, 256>>>(W_bilinear);

    pair_kernel<<<(B_ * P_) / 8, 256>>>(pair_head, pair_tail, b_linear, out);
}

// round 11
// speedup vs baseline: 1.0054x; 1.0054x over previous
#include <cuda_runtime.h>
#include <cuda_bf16.h>
#include <float.h>

// Problem constants
#define B_  8
#define T_  512
#define D_  256
#define S_  64
#define P_  1024
#define R_  12

// Scratch (device globals — no allocation allowed)
__device__ float g_sp[B_ * S_ * D_];            // span-pooled features [B,S,D]
__device__ float g_U [B_ * S_ * R_ * D_];       // U[b,h,r,e]; per-b view: [768, 256]
__device__ float g_S2[B_ * S_ * R_ * S_];       // S2[b][h*R+r][t]  (1.5 MB)
__device__ float g_Lh[B_ * S_ * R_];            // head linear term
__device__ float g_Lt[B_ * S_ * R_];            // tail linear term

// ---------------------------------------------------------------------------
// f32x2 packed-math helpers (sm_10x: fma.rn.f32x2 — 2x fp32 FMA throughput)
// ---------------------------------------------------------------------------
__device__ __forceinline__ unsigned long long ffma2_(unsigned long long a,
                                                     unsigned long long b,
                                                     unsigned long long c) {
    unsigned long long d;
    asm("fma.rn.f32x2 %0, %1, %2, %3;" : "=l"(d) : "l"(a), "l"(b), "l"(c));
    return d;
}
__device__ __forceinline__ unsigned long long pack_dup(float x) {
    unsigned long long d;
    unsigned int xi = __float_as_uint(x);
    asm("mov.b64 %0, {%1, %1};" : "=l"(d) : "r"(xi));
    return d;
}
__device__ __forceinline__ float2 unpack2(unsigned long long v) {
    float2 f;
    asm("mov.b64 {%0, %1}, %2;" : "=f"(f.x), "=f"(f.y) : "l"(v));
    return f;
}

// ---------------------------------------------------------------------------
// Kernel 1: ragged span max-pool + per-span linear projections.
// W_linear staged TRANSPOSED into smem (fixes measured 48B-stride wavefront
// amplification: 12 L1 wavefronts per LDG in the R6 profile).
// ---------------------------------------------------------------------------
#define MAX_SPAN 13

__global__ __launch_bounds__(256)
void pool_linear_kernel(const float* __restrict__ encoded,
                        const float* __restrict__ W_linear,
                        const int*   __restrict__ span_starts,
                        const int*   __restrict__ span_lens)
{
    __shared__ float Wl_s[24][D_];   // [j = part*12+r][dd % 256], 24KB
    __shared__ float sm[D_];

    int bs = blockIdx.x;             // 0..511
    int b  = bs >> 6;
    int s  = bs & (S_ - 1);
    int d  = threadIdx.x;

    // Stage W_linear transposed: element idx has dd = idx/12, r = idx%12.
    #pragma unroll
    for (int it = 0; it < 24; ++it) {
        int idx = it * 256 + threadIdx.x;        // 0..6143
        float v = W_linear[idx];
        int dd = idx / R_;
        int r  = idx - dd * R_;
        Wl_s[(dd >> 8) * R_ + r][dd & (D_ - 1)] = v;
    }

    int start = span_starts[b * S_ + s];
    int len   = span_lens  [b * S_ + s];
    int end   = start + len + 1;     // reference guarantees end <= T
    if (end > T_) end = T_;
    int n = end - start;             // 1..13

    const float* ep = encoded + ((size_t)b * T_ + start) * D_ + d;
    float m = -FLT_MAX;
    #pragma unroll
    for (int i = 0; i < MAX_SPAN; ++i) {
        float v = (i < n) ? ep[(size_t)i * D_] : -FLT_MAX;
        m = fmaxf(m, v);
    }

    sm[d] = m;
    g_sp[(size_t)bs * D_ + d] = m;
    __syncthreads();

    // 24 dot products, 8 warps -> 3 each; operands in smem, conflict-free.
    int w    = threadIdx.x >> 5;
    int lane = threadIdx.x & 31;
    #pragma unroll
    for (int jj = 0; jj < 3; ++jj) {
        int j = w + jj * 8;          // 0..23
        float acc = 0.f;
        #pragma unroll
        for (int i = 0; i < 8; ++i) {
            int dd = i * 32 + lane;
            acc = fmaf(sm[dd], Wl_s[j][dd], acc);
        }
        #pragma unroll
        for (int o = 16; o; o >>= 1)
            acc += __shfl_xor_sync(0xFFFFFFFFu, acc, o);
        if (lane == 0) {
            int r    = j % R_;
            int part = j / R_;
            if (part) g_Lt[bs * R_ + r] = acc;
            else      g_Lh[bs * R_ + r] = acc;
        }
    }
}

// ---------------------------------------------------------------------------
// Kernel 2: U[b,s,r,e] = sum_d sp[b,s,d] * Wb[r,d,e]
// 12 GEMMs: A = g_sp [512 x 256], B = Wb[r] [256 x 256] -> C_r [512 x 256]
// 64x64 tile, BK=16, 128 threads, 8x4 reg tile, f32x2. 384 blocks, occ 4.
// ---------------------------------------------------------------------------
#define BM 64
#define BN 64
#define BK 16

__global__ __launch_bounds__(128, 4)
void ugemm_kernel(const float* __restrict__ Wb)
{
    const int r  = blockIdx.z;
    const int m0 = blockIdx.y * BM;
    const int n0 = blockIdx.x * BN;

    const float* A  = g_sp;                         // [512, 256] row-major
    const float* Bm = Wb + (size_t)r * D_ * D_;     // [256, 256] row-major

    __shared__ float As[BK][BM + 4];   // transposed: As[k][m]
    __shared__ float Bs[BK][BN + 4];

    const int tid = threadIdx.x;       // 0..127

    const int a_row = tid >> 1;            // 0..63
    const int a_k   = (tid & 1) * 8;       // 0 or 8
    const int b_k   = tid >> 3;            // 0..15
    const int b_col = (tid & 7) * 8;       // 0..56

    const int tm  = (tid >> 4) * 8;        // 0..56
    const int tn4 = (tid & 15) * 4;        // 0..60

    unsigned long long acc[8][2];
    #pragma unroll
    for (int i = 0; i < 8; ++i) { acc[i][0] = 0ULL; acc[i][1] = 0ULL; }

    float4 pa0 = *(const float4*)&A [(size_t)(m0 + a_row) * D_ + a_k];
    float4 pa1 = *(const float4*)&A [(size_t)(m0 + a_row) * D_ + a_k + 4];
    float4 pb0 = *(const float4*)&Bm[(size_t)b_k * D_ + n0 + b_col];
    float4 pb1 = *(const float4*)&Bm[(size_t)b_k * D_ + n0 + b_col + 4];

    for (int k0 = 0; k0 < D_; k0 += BK) {
        As[a_k + 0][a_row] = pa0.x;
        As[a_k + 1][a_row] = pa0.y;
        As[a_k + 2][a_row] = pa0.z;
        As[a_k + 3][a_row] = pa0.w;
        As[a_k + 4][a_row] = pa1.x;
        As[a_k + 5][a_row] = pa1.y;
        As[a_k + 6][a_row] = pa1.z;
        As[a_k + 7][a_row] = pa1.w;
        *(float4*)&Bs[b_k][b_col]     = pb0;
        *(float4*)&Bs[b_k][b_col + 4] = pb1;
        __syncthreads();

        if (k0 + BK < D_) {
            pa0 = *(const float4*)&A [(size_t)(m0 + a_row) * D_ + k0 + BK + a_k];
            pa1 = *(const float4*)&A [(size_t)(m0 + a_row) * D_ + k0 + BK + a_k + 4];
            pb0 = *(const float4*)&Bm[(size_t)(k0 + BK + b_k) * D_ + n0 + b_col];
            pb1 = *(const float4*)&Bm[(size_t)(k0 + BK + b_k) * D_ + n0 + b_col + 4];
        }

        #pragma unroll
        for (int k = 0; k < BK; ++k) {
            float4 av0 = *(const float4*)&As[k][tm];
            float4 av1 = *(const float4*)&As[k][tm + 4];
            ulonglong2 bq = *(const ulonglong2*)&Bs[k][tn4];
            unsigned long long bb0 = bq.x, bb1 = bq.y;
            float aa[8] = {av0.x, av0.y, av0.z, av0.w, av1.x, av1.y, av1.z, av1.w};
            #pragma unroll
            for (int i = 0; i < 8; ++i) {
                unsigned long long ad = pack_dup(aa[i]);
                acc[i][0] = ffma2_(ad, bb0, acc[i][0]);
                acc[i][1] = ffma2_(ad, bb1, acc[i][1]);
            }
        }
        __syncthreads();
    }

    #pragma unroll
    for (int i = 0; i < 8; ++i) {
        float2 c01 = unpack2(acc[i][0]);
        float2 c23 = unpack2(acc[i][1]);
        size_t base = ((size_t)(m0 + tm + i) * R_ + r) * D_;
        *(float4*)&g_U[base + n0 + tn4] = make_float4(c01.x, c01.y, c23.x, c23.y);
    }
}

// ---------------------------------------------------------------------------
// Kernel 3: all-pairs score GEMM.
// Per batch b: S2[b] = U2[b] @ sp[b]^T, U2[b]=[768,256], sp[b]=[64,256] (NT).
// 64x64 tile, BK=16, 128 threads, 8x4 reg tile, f32x2. grid (1,12,8)=96 blocks.
// Only 100M MACs total (1/4 of ugemm).
// ---------------------------------------------------------------------------
__global__ __launch_bounds__(128, 4)
void pairgemm_kernel()
{
    const int b  = blockIdx.z;
    const int j0 = blockIdx.y * 64;        // 0..704

    const float* A  = g_U  + (size_t)b * (S_ * R_ * D_);  // [768, 256] row-major
    const float* Bp = g_sp + (size_t)b * (S_ * D_);       // [64, 256] row-major (NT operand)

    __shared__ float As[BK][64 + 4];   // transposed: As[k][j]
    __shared__ float Bs[BK][64 + 4];   // transposed: Bs[k][t]

    const int tid = threadIdx.x;       // 0..127

    // both operands: 64 rows x 16 k per slab, transpose-stored
    const int a_row = tid >> 1;            // 0..63
    const int a_k   = (tid & 1) * 8;       // 0 or 8

    const int tm  = (tid >> 4) * 8;        // j within tile, 0..56
    const int tn4 = (tid & 15) * 4;        // t, 0..60

    unsigned long long acc[8][2];
    #pragma unroll
    for (int i = 0; i < 8; ++i) { acc[i][0] = 0ULL; acc[i][1] = 0ULL; }

    float4 pa0 = *(const float4*)&A [(size_t)(j0 + a_row) * D_ + a_k];
    float4 pa1 = *(const float4*)&A [(size_t)(j0 + a_row) * D_ + a_k + 4];
    float4 pb0 = *(const float4*)&Bp[(size_t)a_row * D_ + a_k];
    float4 pb1 = *(const float4*)&Bp[(size_t)a_row * D_ + a_k + 4];

    for (int k0 = 0; k0 < D_; k0 += BK) {
        As[a_k + 0][a_row] = pa0.x;
        As[a_k + 1][a_row] = pa0.y;
        As[a_k + 2][a_row] = pa0.z;
        As[a_k + 3][a_row] = pa0.w;
        As[a_k + 4][a_row] = pa1.x;
        As[a_k + 5][a_row] = pa1.y;
        As[a_k + 6][a_row] = pa1.z;
        As[a_k + 7][a_row] = pa1.w;
        Bs[a_k + 0][a_row] = pb0.x;
        Bs[a_k + 1][a_row] = pb0.y;
        Bs[a_k + 2][a_row] = pb0.z;
        Bs[a_k + 3][a_row] = pb0.w;
        Bs[a_k + 4][a_row] = pb1.x;
        Bs[a_k + 5][a_row] = pb1.y;
        Bs[a_k + 6][a_row] = pb1.z;
        Bs[a_k + 7][a_row] = pb1.w;
        __syncthreads();

        if (k0 + BK < D_) {
            pa0 = *(const float4*)&A [(size_t)(j0 + a_row) * D_ + k0 + BK + a_k];
            pa1 = *(const float4*)&A [(size_t)(j0 + a_row) * D_ + k0 + BK + a_k + 4];
            pb0 = *(const float4*)&Bp[(size_t)a_row * D_ + k0 + BK + a_k];
            pb1 = *(const float4*)&Bp[(size_t)a_row * D_ + k0 + BK + a_k + 4];
        }

        #pragma unroll
        for (int k = 0; k < BK; ++k) {
            float4 av0 = *(const float4*)&As[k][tm];
            float4 av1 = *(const float4*)&As[k][tm + 4];
            ulonglong2 bq = *(const ulonglong2*)&Bs[k][tn4];
            unsigned long long bb0 = bq.x, bb1 = bq.y;
            float aa[8] = {av0.x, av0.y, av0.z, av0.w, av1.x, av1.y, av1.z, av1.w};
            #pragma unroll
            for (int i = 0; i < 8; ++i) {
                unsigned long long ad = pack_dup(aa[i]);
                acc[i][0] = ffma2_(ad, bb0, acc[i][0]);
                acc[i][1] = ffma2_(ad, bb1, acc[i][1]);
            }
        }
        __syncthreads();
    }

    // store: g_S2[(b*768 + j0+tm+i)*64 + tn4 .. +3]
    #pragma unroll
    for (int i = 0; i < 8; ++i) {
        float2 c01 = unpack2(acc[i][0]);
        float2 c23 = unpack2(acc[i][1]);
        size_t base = ((size_t)b * (S_ * R_) + j0 + tm + i) * S_;
        *(float4*)&g_S2[base + tn4] = make_float4(c01.x, c01.y, c23.x, c23.y);
    }
}

// ---------------------------------------------------------------------------
// Kernel 4: gather + bias + sigmoid. One thread per (pair, r) element.
// out[g*12+r] = sigmoid(S2[b, h*12+r, t] + Lh[b,h,r] + Lt[b,t,r] + bias[r])
// ---------------------------------------------------------------------------
__global__ __launch_bounds__(256)
void gather_kernel(const int*   __restrict__ pair_head,
                   const int*   __restrict__ pair_tail,
                   const float* __restrict__ b_linear,
                   float*       __restrict__ out)
{
    int idx = blockIdx.x * 256 + threadIdx.x;   // 0..98303 (= 8*1024*12 exactly)
    int r = idx % R_;
    int g = idx / R_;                           // pair id 0..8191
    int b = g >> 10;
    int p = g & (P_ - 1);

    int h = pair_head[b * P_ + p];
    int t = pair_tail[b * P_ + p];

    float x = g_S2[((size_t)b * (S_ * R_) + h * R_ + r) * S_ + t]
            + g_Lh[(b * S_ + h) * R_ + r]
            + g_Lt[(b * S_ + t) * R_ + r]
            + b_linear[r];
    out[idx] = 1.f / (1.f + __expf(-x));
}

// ---------------------------------------------------------------------------
extern "C" void kernel_launch(void* const* d_in, const int* in_sizes, int n_in,
                              void* d_out, int out_size)
{
    const float* encoded     = (const float*)d_in[0];  // [8,512,256]
    const float* W_linear    = (const float*)d_in[1];  // [512,12]
    const float* b_linear    = (const float*)d_in[2];  // [12]
    const float* W_bilinear  = (const float*)d_in[3];  // [12,256,256]
    const int*   span_starts = (const int*)  d_in[4];  // [8,64]
    const int*   span_lens   = (const int*)  d_in[5];  // [8,64]
    const int*   pair_head   = (const int*)  d_in[6];  // [8,1024]
    const int*   pair_tail   = (const int*)  d_in[7];  // [8,1024]
    float*       out         = (float*)d_out;          // [8,1024,12]

    pool_linear_kernel<<<B_ * S_, 256>>>(encoded, W_linear, span_starts, span_lens);

    dim3 ggrid(D_ / BN, (B_ * S_) / BM, R_);  // (4, 8, 12) = 384 blocks
    ugemm_kernel<<<ggrid, 128>>>(W_bilinear);

    dim3 pgrid(1, (S_ * R_) / 64, B_);        // (1, 12, 8) = 96 blocks
    pairgemm_kernel<<<pgrid, 128>>>();

    gather_kernel<<<(B_ * P_ * R_) / 256, 256>>>(pair_head, pair_tail, b_linear, out);
}